// round 14
// baseline (speedup 1.0000x reference)
#include <cuda_runtime.h>
#include <cuda_fp16.h>
#include <cstdint>

#define TS 1460
#define NG 2000
#define NREC 16      // uint32 slots per (t,g) record (64B)
#define TCH 16       // timesteps per routing thread

// ---- scratch (static __device__ globals) ----
__device__ float         g_pre [(size_t)TS * NG * NREC];   // ~187 MB
__device__ unsigned char g_gate[(size_t)TS * NG];
__device__ float         g_surf[(size_t)TS * NG];
__device__ float         g_base[(size_t)TS * NG];
__device__ float         g_uh  [2 * 15 * NG];

__constant__ float c_lo[32] = {0.f,0.5f,0.001f,0.3f,20.f,-8.f,1.f,0.1f,0.1f,1e-4f,1.f,1e-4f,0.1f,0.1f,50.f,-8.f,
                               1.f,-5.f,0.f,1.5f,0.f,0.01f,-1.f,0.f,0.f,0.f,50.f,50.f,0.3f,0.01f,0.5f,0.15f};
__constant__ float c_hi[32] = {1.f,3.f,3.f,1.f,300.f,-2.f,5.f,200.f,0.5f,0.9999f,50.f,0.9999f,50.f,100.f,500.f,-2.f,
                               5.f,2.f,5.f,3.f,5.f,0.2f,1.f,0.4f,1.f,1.f,500.f,500.f,20.f,5.f,13.f,1.5f};

__device__ __forceinline__ float sigm(float x) { return 1.f / (1.f + __expf(-x)); }
__device__ __forceinline__ float clip01(float x) { return fminf(fmaxf(x, 1e-6f), 1.f); }
__device__ __forceinline__ void prefetchL2(const void* p) {
    asm volatile("prefetch.global.L2 [%0];" :: "l"(p));
}
// expm1 for x in [0, 0.5]: Horner, rel err < 4e-6.
__device__ __forceinline__ float expm1_poly(float x) {
    float r = 1.f/720.f;
    r = fmaf(r, x, 1.f/120.f);
    r = fmaf(r, x, 1.f/24.f);
    r = fmaf(r, x, 1.f/6.f);
    r = fmaf(r, x, 0.5f);
    r = fmaf(r, x, 1.f);
    return r * x;
}
__device__ __forceinline__ float2 h2pair(float v) {
    unsigned u = __float_as_uint(v);
    __half2 h = *reinterpret_cast<__half2*>(&u);
    return __half22float2(h);
}
__device__ __forceinline__ unsigned packh2(float a, float b) {
    __half2 h = __floats2half2_rn(a, b);
    return *reinterpret_cast<unsigned*>(&h);
}

// ============================================================================
// Kernel 1: per-(t,g) preprocess — softmax -> fp16 pairs (R9 layout), plus
// state-independent forcing precompute:
//  o[0..8]  = 9x half2 raw softmax weights (wi0..5, wa0..5, wb0..5)
//  o[9]=bits o[10]=rain_eff o[11]=snowf_eff o[12]=refreeze_cap
//  o[13]=ddf_pos o[14]=pet
// 2D grid: x covers g, y covers t (no modulo).
// ============================================================================
__global__ void prep_kernel(const float* __restrict__ xphy, const float* __restrict__ wts,
                            const float* __restrict__ hyb) {
    int g = blockIdx.x * blockDim.x + threadIdx.x;
    int t = blockIdx.y;
    if (g >= NG) return;
    size_t i = (size_t)t * NG + g;

    const float4* wsrc = (const float4*)(wts + i * 24);
    float v[24];
#pragma unroll
    for (int k = 0; k < 6; k++) {
        float4 q = wsrc[k];
        v[4*k] = q.x; v[4*k+1] = q.y; v[4*k+2] = q.z; v[4*k+3] = q.w;
    }
    float w[18];
#pragma unroll
    for (int grp = 0; grp < 3; grp++) {
        float m = v[grp*6];
#pragma unroll
        for (int k = 1; k < 6; k++) m = fmaxf(m, v[grp*6 + k]);
        float e[6], s = 0.f;
#pragma unroll
        for (int k = 0; k < 6; k++) { e[k] = __expf(v[grp*6 + k] - m); s += e[k]; }
        float inv = 1.f / s;
#pragma unroll
        for (int k = 0; k < 6; k++) w[grp*6 + k] = e[k] * inv;
    }
    unsigned bits = 0;
#pragma unroll
    for (int k = 0; k < 6; k++) bits |= (v[18 + k] > 0.f) ? (1u << k) : 0u;

    // per-cell params needed for forcing (L2-hot: hyb is 256 KB)
    const float* h = hyb + (size_t)g * 32;
    float Tbf = c_lo[17] + sigm(h[17]) * (c_hi[17] - c_lo[17]);
    float Kf  = c_lo[18] + sigm(h[18]) * (c_hi[18] - c_lo[18]);
    float Tbm = c_lo[22] + sigm(h[22]) * (c_hi[22] - c_lo[22]);
    float fc  = c_lo[24] + sigm(h[24]) * (c_hi[24] - c_lo[24]);
    float fs  = c_lo[25] + sigm(h[25]) * (c_hi[25] - c_lo[25]);
    float cc  = fc * (1.f - fs);

    const float prcp = xphy[i*3 + 0], temp = xphy[i*3 + 1], pet = xphy[i*3 + 2];
    float canopy = pet * cc;
    float gb2 = ((bits >> 2) & 1u) ? 1.f : 0.f;
    float gb3 = ((bits >> 3) & 1u) ? 1.f : 0.f;
    float rain_eff  = (temp >= 0.f) ? fmaxf(prcp - canopy * gb2, 0.f) : 0.f;
    float snowf_eff = (temp <  0.f) ? fmaxf(prcp - canopy * gb3, 0.f) : 0.f;
    float refreeze_cap = Kf * fmaxf(Tbf - temp, 0.f);
    float ddf_pos = fmaxf(temp - Tbm, 0.f);

    unsigned o[16];
#pragma unroll
    for (int k = 0; k < 9; k++) o[k] = packh2(w[2*k], w[2*k+1]);
    o[9]  = bits;
    o[10] = __float_as_uint(rain_eff);
    o[11] = __float_as_uint(snowf_eff);
    o[12] = __float_as_uint(refreeze_cap);
    o[13] = __float_as_uint(ddf_pos);
    o[14] = __float_as_uint(pet);
    o[15] = 0u;

    float4* dst = (float4*)(g_pre + i * NREC);
#pragma unroll
    for (int k = 0; k < 4; k++)
        dst[k] = make_float4(__uint_as_float(o[4*k]), __uint_as_float(o[4*k+1]),
                             __uint_as_float(o[4*k+2]), __uint_as_float(o[4*k+3]));
    g_gate[i] = (unsigned char)bits;
}

// ============================================================================
// Kernel 2: per-cell unit-hydrograph weights
// ============================================================================
__global__ void uh_kernel(const float* __restrict__ hyb) {
    int g = blockIdx.x * blockDim.x + threadIdx.x;
    if (g >= NG) return;
    const float* h = hyb + (size_t)g * 32;
    float a1 = c_lo[28] + sigm(h[28]) * (c_hi[28] - c_lo[28]);
    float b1 = c_lo[29] + sigm(h[29]) * (c_hi[29] - c_lo[29]);
    float a2 = c_lo[30] + sigm(h[30]) * (c_hi[30] - c_lo[30]);
    float b2 = c_lo[31] + sigm(h[31]) * (c_hi[31] - c_lo[31]);
    float ib1 = 1.f / b1, ib2 = 1.f / b2;
    float lw1[15], lw2[15], m1 = -1e30f, m2 = -1e30f;
#pragma unroll
    for (int k = 0; k < 15; k++) {
        float kk = (float)(k + 1);
        float lk = __logf(kk);
        lw1[k] = (a1 - 1.f) * lk - kk * ib1;
        lw2[k] = (a2 - 1.f) * lk - kk * ib2;
        m1 = fmaxf(m1, lw1[k]); m2 = fmaxf(m2, lw2[k]);
    }
    float e1[15], e2[15], s1 = 0.f, s2 = 0.f;
#pragma unroll
    for (int k = 0; k < 15; k++) {
        e1[k] = __expf(lw1[k] - m1); s1 += e1[k];
        e2[k] = __expf(lw2[k] - m2); s2 += e2[k];
    }
    float i1 = 1.f / s1, i2 = 1.f / s2;
#pragma unroll
    for (int k = 0; k < 15; k++) {
        g_uh[k * NG + g]        = e1[k] * i1;
        g_uh[(15 + k) * NG + g] = e2[k] * i2;
    }
}

// ============================================================================
// Kernel 3: sequential scan — R9 structure (1 cell/thread, one warp per SM,
// depth-2 register pipeline + L2 prefetch), snow-module head precomputed.
// ============================================================================
__global__ void __launch_bounds__(32, 1) scan_kernel(const float* __restrict__ hyb) {
    int g = blockIdx.x * 32 + threadIdx.x;
    if (g >= NG) return;
    const float* h = hyb + (size_t)g * 32;
    float P[32];
#pragma unroll
    for (int i = 0; i < 32; i++) P[i] = c_lo[i] + sigm(h[i]) * (c_hi[i] - c_lo[i]);

    const float ddfmin = P[19], ddfplus = P[20], Kcum = P[21], swi = P[23];
    const float msw1 = P[26];
    const float inv_m1 = 1.f / P[26], inv_m2 = 1.f / P[27];
    const float inf_pc = P[0], hbv_beta = P[1], vic_b = P[2], hm_a = P[3];
    const float perc_coef = P[10] / (1.f - P[11]);
    const float perc_sfc = P[11], crise = P[12];
    const float inv_x3a = 1.f / P[4];
    const float p10a = exp2f(P[5] * 3.3219280948873623f);   // 10^bfc1
    const float bfn1 = P[6], bfmax1 = P[7], lam = P[8];
    const float c_lam = bfmax1 / expm1f(lam);
    const float thresh = P[9];
    const float c_th = bfmax1 / (1.f - thresh);
    const float inv_x3b = 1.f / P[14];
    const float p10b = exp2f(P[15] * 3.3219280948873623f);  // 10^bfc2
    const float bfn2 = P[16], bfmax2 = P[13];

    float snow = 1e-6f, liq = 1e-6f, cum = 1e-6f, sw1 = 1e-6f, sw2 = 1e-6f;

    const float4* rec = (const float4*)g_pre;
    size_t r0 = ((size_t)0 * NG + g) * 4;
    size_t r1 = ((size_t)1 * NG + g) * 4;
    float4 c0 = __ldcs(rec+r0), c1 = __ldcs(rec+r0+1), c2 = __ldcs(rec+r0+2), c3 = __ldcs(rec+r0+3);
    float4 n0 = __ldcs(rec+r1), n1 = __ldcs(rec+r1+1), n2 = __ldcs(rec+r1+2), n3 = __ldcs(rec+r1+3);
#pragma unroll
    for (int tp = 2; tp < 8; tp++)
        prefetchL2((const char*)(rec + ((size_t)tp * NG + g) * 4));

    for (int t = 0; t < TS; t++) {
        int tpf = t + 8; if (tpf >= TS) tpf = TS - 1;
        prefetchL2((const char*)(rec + ((size_t)tpf * NG + g) * 4));

        int t2 = t + 2; if (t2 >= TS) t2 = TS - 1;
        size_t r2 = ((size_t)t2 * NG + g) * 4;
        float4 m0 = __ldcs(rec+r2),   m1v = __ldcs(rec+r2+1),
               m2v = __ldcs(rec+r2+2), m3 = __ldcs(rec+r2+3);

        // unpack current record: 9 half2 pairs + bits + forcing
        float2 pw0 = h2pair(c0.x), pw1 = h2pair(c0.y), pw2 = h2pair(c0.z);
        float2 pa0 = h2pair(c0.w), pa1 = h2pair(c1.x), pa2 = h2pair(c1.y);
        float2 pb0 = h2pair(c1.z), pb1 = h2pair(c1.w), pb2 = h2pair(c2.x);
        const float wi0 = pw0.x, wi1 = pw0.y, wi2 = pw1.x, wi3 = pw1.y, wi4 = pw2.x, wi5 = pw2.y;
        const float wa0 = pa0.x, wa1 = pa0.y, wa2 = pa1.x, wa3 = pa1.y, wa4 = pa2.x, wa5 = pa2.y;
        const float wb0 = pb0.x, wb1 = pb0.y, wb2 = pb1.x, wb3 = pb1.y, wb4 = pb2.x, wb5 = pb2.y;
        const unsigned bits = __float_as_uint(c2.y);
        const float rain_eff = c2.z, snowf_eff = c2.w;
        const float refreeze_cap = c3.x, ddf_pos = c3.y, pet = c3.z;
        const float gb0 = (bits & 1u)        ? 1.f : 0.f;
        const float gb1 = ((bits >> 1) & 1u) ? 1.f : 0.f;

        // --- snow module (state-dependent part only) ---
        float refreeze = fminf(liq, refreeze_cap);
        snow = snow + snowf_eff + refreeze;
        liq  = liq - refreeze;
        float ddf  = ddfmin + ddfplus * (1.f - __expf(-Kcum * cum));
        float melt = fminf(snow, ddf * ddf_pos);
        snow -= melt;
        cum = (snow < 1e-6f) ? 1e-6f : (cum + melt);
        liq += melt;
        float overflow = fmaxf(liq - swi * snow, 0.f);
        liq -= overflow;
        float wavail = rain_eff + overflow;

        // --- infiltration blend ---
        float sat1 = clip01(sw1 * inv_m1);
        float dry1 = clip01(1.f - sat1);
        float o1 = 1.f - __powf(sat1, hbv_beta);
        float o2 = __powf(dry1, vic_b);
        float fsum = wi0 * inf_pc + wi1 * o1 + wi2 * o2 + wi3 * (hm_a * dry1)
                   + wi4 * (1.f - sat1 * sat1) + wi5;
        float infil = wavail * fsum;
        sw1 += infil;
        float excess = fmaxf(sw1 - msw1, 0.f);
        sw1 -= excess;
        float surf = wavail - infil + excess;

        // --- percolation / capillary rise / ET ---
        sat1 = clip01(sw1 * inv_m1);
        float perc = gb0 * perc_coef * fmaxf(sat1 - perc_sfc, 0.f);
        perc = fminf(perc, sw1);
        sw1 -= perc; sw2 += perc;
        float sat2 = clip01(sw2 * inv_m2);
        sat1 = clip01(sw1 * inv_m1);
        float capi = fminf(gb1 * crise * (1.f - sat1) * sat2, sw2);
        sw2 -= capi; sw1 += capi;
        sat1 = clip01(sw1 * inv_m1);
        float et = fminf(pet * sat1, sw1);
        sw1 -= et;
        sat1 = clip01(sw1 * inv_m1);

        // --- baseflow 1 blend ---   (1+r^4)^(-1/4) == sqrtf(rsqrtf(q))
        float ra = sw1 * inv_x3a; float ra2 = ra * ra; float qa = 1.f + ra2 * ra2;
        float b0v = sw1 * (1.f - sqrtf(rsqrtf(qa)));
        float b1v = p10a * sw1;
        float b2v = bfmax1 * __powf(sat1, bfn1);
        float b3v = bfmax1 * sat1;
        float b4v = c_lam * expm1_poly(lam * sat1);
        float b5v = c_th * fmaxf(sat1 - thresh, 0.f);
        float bf1 = fminf(wa0*b0v + wa1*b1v + wa2*b2v + wa3*b3v + wa4*b4v + wa5*b5v, sw1);
        sw1 -= bf1;

        // --- baseflow 2 blend ---
        float s2c = clip01(sw2 * inv_m2);
        float rb = sw2 * inv_x3b; float rb2 = rb * rb; float qb = 1.f + rb2 * rb2;
        float d0 = sw2 * (1.f - sqrtf(rsqrtf(qb)));
        float d1 = p10b * sw2;
        float d2 = bfmax2 * __powf(s2c, bfn2);
        float d3 = bfmax2 * s2c;
        float d4 = bfmax2 * s2c * s2c;
        float d5 = d1 * s2c;
        float bf2 = fminf(wb0*d0 + wb1*d1 + wb2*d2 + wb3*d3 + wb4*d4 + wb5*d5, sw2);
        sw2 -= bf2;

        g_surf[(size_t)t * NG + g] = surf;
        g_base[(size_t)t * NG + g] = bf1 + bf2;

        c0 = n0; c1 = n1; c2 = n2; c3 = n3;
        n0 = m0; n1 = m1v; n2 = m2v; n3 = m3;
    }
}

// ============================================================================
// Kernel 4: 15-tap UH routing + gating + final sum.
// ============================================================================
__global__ void __launch_bounds__(128) route_kernel(float* __restrict__ out) {
    int g  = blockIdx.x * 128 + threadIdx.x;
    int t0 = blockIdx.y * TCH;
    if (g >= NG) return;
    float u1[15], u2[15];
#pragma unroll
    for (int k = 0; k < 15; k++) {
        u1[k] = g_uh[k * NG + g];
        u2[k] = g_uh[(15 + k) * NG + g];
    }
    float s[TCH + 14], b[TCH + 14];
#pragma unroll
    for (int i = 0; i < TCH + 14; i++) {
        int tt = t0 - 14 + i;
        bool ok = (tt >= 0) && (tt < TS);
        s[i] = ok ? g_surf[(size_t)tt * NG + g] : 0.f;
        b[i] = ok ? g_base[(size_t)tt * NG + g] : 0.f;
    }
#pragma unroll
    for (int j = 0; j < TCH; j++) {
        int t = t0 + j;
        if (t < TS) {
            float cs = 0.f, cb = 0.f;
#pragma unroll
            for (int l = 0; l < 15; l++) {
                cs += u1[l] * s[14 + j - l];
                cb += u2[l] * b[14 + j - l];
            }
            unsigned bits = g_gate[(size_t)t * NG + g];
            float g4 = (float)((bits >> 4) & 1);
            float g5 = (float)((bits >> 5) & 1);
            out[(size_t)t * NG + g] = g4 * cs + (1.f - g4) * s[14 + j]
                                    + g5 * cb + (1.f - g5) * b[14 + j];
        }
    }
}

// ============================================================================
extern "C" void kernel_launch(void* const* d_in, const int* in_sizes, int n_in,
                              void* d_out, int out_size) {
    const float* xphy = nullptr; const float* wts = nullptr; const float* hyb = nullptr;
    for (int i = 0; i < n_in; i++) {
        if (in_sizes[i] == TS * NG * 3)       xphy = (const float*)d_in[i];
        else if (in_sizes[i] == TS * NG * 24) wts  = (const float*)d_in[i];
        else if (in_sizes[i] == NG * 32)      hyb  = (const float*)d_in[i];
    }
    float* out = (float*)d_out;                  // (1460, 2000)

    dim3 pg((NG + 255) / 256, TS);
    prep_kernel<<<pg, 256>>>(xphy, wts, hyb);
    uh_kernel<<<(NG + 127) / 128, 128>>>(hyb);
    scan_kernel<<<(NG + 31) / 32, 32>>>(hyb);
    dim3 rg((NG + 127) / 128, (TS + TCH - 1) / TCH);
    route_kernel<<<rg, 128>>>(out);
}

// round 15
// speedup vs baseline: 1.3211x; 1.3211x over previous
#include <cuda_runtime.h>
#include <cuda_fp16.h>
#include <cstdint>

#define TS 1460
#define NG 2000
#define NREC 16      // uint32 slots per (t,g) record (64B)
#define TCH 16       // timesteps per routing thread

// ---- scratch (static __device__ globals) ----
__device__ float         g_pre [(size_t)TS * NG * NREC];   // ~187 MB
__device__ unsigned char g_gate[(size_t)TS * NG];
__device__ float         g_surf[(size_t)TS * NG];
__device__ float         g_base[(size_t)TS * NG];
__device__ float         g_uh  [2 * 15 * NG];

__constant__ float c_lo[32] = {0.f,0.5f,0.001f,0.3f,20.f,-8.f,1.f,0.1f,0.1f,1e-4f,1.f,1e-4f,0.1f,0.1f,50.f,-8.f,
                               1.f,-5.f,0.f,1.5f,0.f,0.01f,-1.f,0.f,0.f,0.f,50.f,50.f,0.3f,0.01f,0.5f,0.15f};
__constant__ float c_hi[32] = {1.f,3.f,3.f,1.f,300.f,-2.f,5.f,200.f,0.5f,0.9999f,50.f,0.9999f,50.f,100.f,500.f,-2.f,
                               5.f,2.f,5.f,3.f,5.f,0.2f,1.f,0.4f,1.f,1.f,500.f,500.f,20.f,5.f,13.f,1.5f};

__device__ __forceinline__ float sigm(float x) { return 1.f / (1.f + __expf(-x)); }
__device__ __forceinline__ float clip01(float x) { return fminf(fmaxf(x, 1e-6f), 1.f); }
__device__ __forceinline__ void prefetchL2(const void* p) {
    asm volatile("prefetch.global.L2 [%0];" :: "l"(p));
}
// expm1 for x in [0, 0.5]: Horner, rel err < 4e-6.
__device__ __forceinline__ float expm1_poly(float x) {
    float r = 1.f/720.f;
    r = fmaf(r, x, 1.f/120.f);
    r = fmaf(r, x, 1.f/24.f);
    r = fmaf(r, x, 1.f/6.f);
    r = fmaf(r, x, 0.5f);
    r = fmaf(r, x, 1.f);
    return r * x;
}
__device__ __forceinline__ float2 h2pair(float v) {
    unsigned u = __float_as_uint(v);
    __half2 h = *reinterpret_cast<__half2*>(&u);
    return __half22float2(h);
}
__device__ __forceinline__ unsigned packh2(float a, float b) {
    __half2 h = __floats2half2_rn(a, b);
    return *reinterpret_cast<unsigned*>(&h);
}

// ============================================================================
// Kernel 1: per-(t,g) preprocess — softmax -> fp16 pairs, gate bits, met.
// (exact R9 version: no hyb reads, flat 1D grid)
// ============================================================================
__global__ void prep_kernel(const float* __restrict__ xphy, const float* __restrict__ wts) {
    size_t i = (size_t)blockIdx.x * blockDim.x + threadIdx.x;
    if (i >= (size_t)TS * NG) return;
    const float4* wsrc = (const float4*)(wts + i * 24);
    float v[24];
#pragma unroll
    for (int k = 0; k < 6; k++) {
        float4 q = wsrc[k];
        v[4*k] = q.x; v[4*k+1] = q.y; v[4*k+2] = q.z; v[4*k+3] = q.w;
    }
    float w[18];
#pragma unroll
    for (int grp = 0; grp < 3; grp++) {
        float m = v[grp*6];
#pragma unroll
        for (int k = 1; k < 6; k++) m = fmaxf(m, v[grp*6 + k]);
        float e[6], s = 0.f;
#pragma unroll
        for (int k = 0; k < 6; k++) { e[k] = __expf(v[grp*6 + k] - m); s += e[k]; }
        float inv = 1.f / s;
#pragma unroll
        for (int k = 0; k < 6; k++) w[grp*6 + k] = e[k] * inv;
    }
    unsigned bits = 0;
#pragma unroll
    for (int k = 0; k < 6; k++) bits |= (v[18 + k] > 0.f) ? (1u << k) : 0u;

    unsigned o[16];
#pragma unroll
    for (int k = 0; k < 9; k++) o[k] = packh2(w[2*k], w[2*k+1]);
    o[9]  = bits;
    o[10] = __float_as_uint(xphy[i*3 + 0]);   // prcp
    o[11] = __float_as_uint(xphy[i*3 + 1]);   // temp
    o[12] = __float_as_uint(xphy[i*3 + 2]);   // pet
    o[13] = 0u; o[14] = 0u; o[15] = 0u;

    float4* dst = (float4*)(g_pre + i * NREC);
#pragma unroll
    for (int k = 0; k < 4; k++)
        dst[k] = make_float4(__uint_as_float(o[4*k]), __uint_as_float(o[4*k+1]),
                             __uint_as_float(o[4*k+2]), __uint_as_float(o[4*k+3]));
    g_gate[i] = (unsigned char)bits;
}

// ============================================================================
// Kernel 2: per-cell unit-hydrograph weights
// ============================================================================
__global__ void uh_kernel(const float* __restrict__ hyb) {
    int g = blockIdx.x * blockDim.x + threadIdx.x;
    if (g >= NG) return;
    const float* h = hyb + (size_t)g * 32;
    float a1 = c_lo[28] + sigm(h[28]) * (c_hi[28] - c_lo[28]);
    float b1 = c_lo[29] + sigm(h[29]) * (c_hi[29] - c_lo[29]);
    float a2 = c_lo[30] + sigm(h[30]) * (c_hi[30] - c_lo[30]);
    float b2 = c_lo[31] + sigm(h[31]) * (c_hi[31] - c_lo[31]);
    float ib1 = 1.f / b1, ib2 = 1.f / b2;
    float lw1[15], lw2[15], m1 = -1e30f, m2 = -1e30f;
#pragma unroll
    for (int k = 0; k < 15; k++) {
        float kk = (float)(k + 1);
        float lk = __logf(kk);
        lw1[k] = (a1 - 1.f) * lk - kk * ib1;
        lw2[k] = (a2 - 1.f) * lk - kk * ib2;
        m1 = fmaxf(m1, lw1[k]); m2 = fmaxf(m2, lw2[k]);
    }
    float e1[15], e2[15], s1 = 0.f, s2 = 0.f;
#pragma unroll
    for (int k = 0; k < 15; k++) {
        e1[k] = __expf(lw1[k] - m1); s1 += e1[k];
        e2[k] = __expf(lw2[k] - m2); s2 += e2[k];
    }
    float i1 = 1.f / s1, i2 = 1.f / s2;
#pragma unroll
    for (int k = 0; k < 15; k++) {
        g_uh[k * NG + g]        = e1[k] * i1;
        g_uh[(15 + k) * NG + g] = e2[k] * i2;
    }
}

// ============================================================================
// One scan step (exact R9 math). Consumes record (c0..c3), updates state,
// writes surf/base.
// ============================================================================
struct SP {   // per-cell scan params
    float ddfmin, ddfplus, Kcum, swi, msw1, inv_m1, inv_m2;
    float inf_pc, hbv_beta, vic_b, hm_a, cc;
    float perc_coef, perc_sfc, crise;
    float inv_x3a, p10a, bfn1, bfmax1, lam, c_lam, thresh, c_th;
    float inv_x3b, p10b, bfn2, bfmax2;
    float Tbf, Kf, Tbm;
};

__device__ __forceinline__ void scan_step(
    const SP& sp, int t, int g,
    float& snow, float& liq, float& cum, float& sw1, float& sw2,
    const float4& c0, const float4& c1, const float4& c2, const float4& c3)
{
    float2 pw0 = h2pair(c0.x), pw1 = h2pair(c0.y), pw2 = h2pair(c0.z);
    float2 pa0 = h2pair(c0.w), pa1 = h2pair(c1.x), pa2 = h2pair(c1.y);
    float2 pb0 = h2pair(c1.z), pb1 = h2pair(c1.w), pb2 = h2pair(c2.x);
    const float wi0 = pw0.x, wi1 = pw0.y, wi2 = pw1.x, wi3 = pw1.y, wi4 = pw2.x, wi5 = pw2.y;
    const float wa0 = pa0.x, wa1 = pa0.y, wa2 = pa1.x, wa3 = pa1.y, wa4 = pa2.x, wa5 = pa2.y;
    const float wb0 = pb0.x, wb1 = pb0.y, wb2 = pb1.x, wb3 = pb1.y, wb4 = pb2.x, wb5 = pb2.y;
    const unsigned bits = __float_as_uint(c2.y);
    const float prcp = c2.z, temp = c2.w, pet = c3.x;
    const float gb0 = (bits & 1u)        ? 1.f : 0.f;
    const float gb1 = ((bits >> 1) & 1u) ? 1.f : 0.f;
    const float gb2 = ((bits >> 2) & 1u) ? 1.f : 0.f;
    const float gb3 = ((bits >> 3) & 1u) ? 1.f : 0.f;

    // --- snow module ---
    float rain  = (temp >= 0.f) ? prcp : 0.f;
    float snowf = (temp <  0.f) ? prcp : 0.f;
    float canopy = pet * sp.cc;
    rain  = fmaxf(rain  - canopy * gb2, 0.f);
    snowf = fmaxf(snowf - canopy * gb3, 0.f);
    float refreeze = fminf(liq, sp.Kf * fmaxf(sp.Tbf - temp, 0.f));
    snow = snow + snowf + refreeze;
    liq  = liq - refreeze;
    float ddf  = sp.ddfmin + sp.ddfplus * (1.f - __expf(-sp.Kcum * cum));
    float melt = fminf(snow, ddf * fmaxf(temp - sp.Tbm, 0.f));
    snow -= melt;
    cum = (snow < 1e-6f) ? 1e-6f : (cum + melt);
    liq += melt;
    float overflow = fmaxf(liq - sp.swi * snow, 0.f);
    liq -= overflow;
    float wavail = rain + overflow;

    // --- infiltration blend ---
    float sat1 = clip01(sw1 * sp.inv_m1);
    float dry1 = clip01(1.f - sat1);
    float o1 = 1.f - __powf(sat1, sp.hbv_beta);
    float o2 = __powf(dry1, sp.vic_b);
    float fsum = wi0 * sp.inf_pc + wi1 * o1 + wi2 * o2 + wi3 * (sp.hm_a * dry1)
               + wi4 * (1.f - sat1 * sat1) + wi5;
    float infil = wavail * fsum;
    sw1 += infil;
    float excess = fmaxf(sw1 - sp.msw1, 0.f);
    sw1 -= excess;
    float surf = wavail - infil + excess;

    // --- percolation / capillary rise / ET ---
    sat1 = clip01(sw1 * sp.inv_m1);
    float perc = gb0 * sp.perc_coef * fmaxf(sat1 - sp.perc_sfc, 0.f);
    perc = fminf(perc, sw1);
    sw1 -= perc; sw2 += perc;
    float sat2 = clip01(sw2 * sp.inv_m2);
    sat1 = clip01(sw1 * sp.inv_m1);
    float capi = fminf(gb1 * sp.crise * (1.f - sat1) * sat2, sw2);
    sw2 -= capi; sw1 += capi;
    sat1 = clip01(sw1 * sp.inv_m1);
    float et = fminf(pet * sat1, sw1);
    sw1 -= et;
    sat1 = clip01(sw1 * sp.inv_m1);

    // --- baseflow 1 blend ---   (1+r^4)^(-1/4) == sqrtf(rsqrtf(q))
    float ra = sw1 * sp.inv_x3a; float ra2 = ra * ra; float qa = 1.f + ra2 * ra2;
    float b0v = sw1 * (1.f - sqrtf(rsqrtf(qa)));
    float b1v = sp.p10a * sw1;
    float b2v = sp.bfmax1 * __powf(sat1, sp.bfn1);
    float b3v = sp.bfmax1 * sat1;
    float b4v = sp.c_lam * expm1_poly(sp.lam * sat1);
    float b5v = sp.c_th * fmaxf(sat1 - sp.thresh, 0.f);
    float bf1 = fminf(wa0*b0v + wa1*b1v + wa2*b2v + wa3*b3v + wa4*b4v + wa5*b5v, sw1);
    sw1 -= bf1;

    // --- baseflow 2 blend ---
    float s2c = clip01(sw2 * sp.inv_m2);
    float rb = sw2 * sp.inv_x3b; float rb2 = rb * rb; float qb = 1.f + rb2 * rb2;
    float d0 = sw2 * (1.f - sqrtf(rsqrtf(qb)));
    float d1 = sp.p10b * sw2;
    float d2 = sp.bfmax2 * __powf(s2c, sp.bfn2);
    float d3 = sp.bfmax2 * s2c;
    float d4 = sp.bfmax2 * s2c * s2c;
    float d5 = d1 * s2c;
    float bf2 = fminf(wb0*d0 + wb1*d1 + wb2*d2 + wb3*d3 + wb4*d4 + wb5*d5, sw2);
    sw2 -= bf2;

    g_surf[(size_t)t * NG + g] = surf;
    g_base[(size_t)t * NG + g] = bf1 + bf2;
}

// ============================================================================
// Kernel 3: sequential scan — R9 structure, t-loop unrolled x2 with a
// rotation-free 3-buffer schedule (same 3 live record sets as R9, half the
// register rotation and loop overhead).
// ============================================================================
__global__ void __launch_bounds__(32, 1) scan_kernel(const float* __restrict__ hyb) {
    int g = blockIdx.x * 32 + threadIdx.x;
    if (g >= NG) return;
    const float* h = hyb + (size_t)g * 32;
    float P[32];
#pragma unroll
    for (int i = 0; i < 32; i++) P[i] = c_lo[i] + sigm(h[i]) * (c_hi[i] - c_lo[i]);

    SP sp;
    sp.cc = P[24] * (1.f - P[25]);
    sp.Tbf = P[17]; sp.Kf = P[18]; sp.ddfmin = P[19]; sp.ddfplus = P[20];
    sp.Kcum = P[21]; sp.Tbm = P[22]; sp.swi = P[23];
    sp.msw1 = P[26]; sp.inv_m1 = 1.f / P[26]; sp.inv_m2 = 1.f / P[27];
    sp.inf_pc = P[0]; sp.hbv_beta = P[1]; sp.vic_b = P[2]; sp.hm_a = P[3];
    sp.perc_coef = P[10] / (1.f - P[11]); sp.perc_sfc = P[11]; sp.crise = P[12];
    sp.inv_x3a = 1.f / P[4];
    sp.p10a = exp2f(P[5] * 3.3219280948873623f);
    sp.bfn1 = P[6]; sp.bfmax1 = P[7]; sp.lam = P[8];
    sp.c_lam = P[7] / expm1f(P[8]);
    sp.thresh = P[9]; sp.c_th = P[7] / (1.f - P[9]);
    sp.inv_x3b = 1.f / P[14];
    sp.p10b = exp2f(P[15] * 3.3219280948873623f);
    sp.bfn2 = P[16]; sp.bfmax2 = P[13];

    float snow = 1e-6f, liq = 1e-6f, cum = 1e-6f, sw1 = 1e-6f, sw2 = 1e-6f;

    const float4* rec = (const float4*)g_pre;
    size_t r0 = ((size_t)0 * NG + g) * 4;
    size_t r1 = ((size_t)1 * NG + g) * 4;
    float4 c0 = __ldcs(rec+r0), c1 = __ldcs(rec+r0+1), c2 = __ldcs(rec+r0+2), c3 = __ldcs(rec+r0+3);
    float4 n0 = __ldcs(rec+r1), n1 = __ldcs(rec+r1+1), n2 = __ldcs(rec+r1+2), n3 = __ldcs(rec+r1+3);
#pragma unroll
    for (int tp = 2; tp < 8; tp++)
        prefetchL2((const char*)(rec + ((size_t)tp * NG + g) * 4));

#pragma unroll 1
    for (int t = 0; t < TS; t += 2) {
        // L2 prefetch: two lines, 8..9 steps ahead (one per step, same as R9)
        int tp8 = t + 8; if (tp8 >= TS) tp8 = TS - 1;
        int tp9 = t + 9; if (tp9 >= TS) tp9 = TS - 1;
        prefetchL2((const char*)(rec + ((size_t)tp8 * NG + g) * 4));
        prefetchL2((const char*)(rec + ((size_t)tp9 * NG + g) * 4));

        // load t+2 (consumed two bodies later)
        int t2 = t + 2; if (t2 >= TS) t2 = TS - 1;
        size_t r2 = ((size_t)t2 * NG + g) * 4;
        float4 m0 = __ldcs(rec+r2),  m1v = __ldcs(rec+r2+1),
               m2v = __ldcs(rec+r2+2), m3 = __ldcs(rec+r2+3);

        // body A: step t (c becomes dead after this)
        scan_step(sp, t, g, snow, liq, cum, sw1, sw2, c0, c1, c2, c3);

        // load t+3 (consumed two bodies later)
        int t3 = t + 3; if (t3 >= TS) t3 = TS - 1;
        size_t r3 = ((size_t)t3 * NG + g) * 4;
        float4 q0 = __ldcs(rec+r3),  q1 = __ldcs(rec+r3+1),
               q2 = __ldcs(rec+r3+2), q3 = __ldcs(rec+r3+3);

        // body B: step t+1
        scan_step(sp, t + 1, g, snow, liq, cum, sw1, sw2, n0, n1, n2, n3);

        // single rotation per 2 steps
        c0 = m0; c1 = m1v; c2 = m2v; c3 = m3;
        n0 = q0; n1 = q1;  n2 = q2;  n3 = q3;
    }
}

// ============================================================================
// Kernel 4: 15-tap UH routing + gating + final sum.
// ============================================================================
__global__ void __launch_bounds__(128) route_kernel(float* __restrict__ out) {
    int g  = blockIdx.x * 128 + threadIdx.x;
    int t0 = blockIdx.y * TCH;
    if (g >= NG) return;
    float u1[15], u2[15];
#pragma unroll
    for (int k = 0; k < 15; k++) {
        u1[k] = g_uh[k * NG + g];
        u2[k] = g_uh[(15 + k) * NG + g];
    }
    float s[TCH + 14], b[TCH + 14];
#pragma unroll
    for (int i = 0; i < TCH + 14; i++) {
        int tt = t0 - 14 + i;
        bool ok = (tt >= 0) && (tt < TS);
        s[i] = ok ? g_surf[(size_t)tt * NG + g] : 0.f;
        b[i] = ok ? g_base[(size_t)tt * NG + g] : 0.f;
    }
#pragma unroll
    for (int j = 0; j < TCH; j++) {
        int t = t0 + j;
        if (t < TS) {
            float cs = 0.f, cb = 0.f;
#pragma unroll
            for (int l = 0; l < 15; l++) {
                cs += u1[l] * s[14 + j - l];
                cb += u2[l] * b[14 + j - l];
            }
            unsigned bits = g_gate[(size_t)t * NG + g];
            float g4 = (float)((bits >> 4) & 1);
            float g5 = (float)((bits >> 5) & 1);
            out[(size_t)t * NG + g] = g4 * cs + (1.f - g4) * s[14 + j]
                                    + g5 * cb + (1.f - g5) * b[14 + j];
        }
    }
}

// ============================================================================
extern "C" void kernel_launch(void* const* d_in, const int* in_sizes, int n_in,
                              void* d_out, int out_size) {
    const float* xphy = nullptr; const float* wts = nullptr; const float* hyb = nullptr;
    for (int i = 0; i < n_in; i++) {
        if (in_sizes[i] == TS * NG * 3)       xphy = (const float*)d_in[i];
        else if (in_sizes[i] == TS * NG * 24) wts  = (const float*)d_in[i];
        else if (in_sizes[i] == NG * 32)      hyb  = (const float*)d_in[i];
    }
    float* out = (float*)d_out;                  // (1460, 2000)

    size_t total = (size_t)TS * NG;
    prep_kernel<<<(unsigned)((total + 255) / 256), 256>>>(xphy, wts);
    uh_kernel<<<(NG + 127) / 128, 128>>>(hyb);
    scan_kernel<<<(NG + 31) / 32, 32>>>(hyb);
    dim3 rg((NG + 127) / 128, (TS + TCH - 1) / TCH);
    route_kernel<<<rg, 128>>>(out);
}

// round 17
// speedup vs baseline: 1.3455x; 1.0185x over previous
#include <cuda_runtime.h>
#include <cuda_fp16.h>
#include <cstdint>

#define TS 1460
#define NG 2000
#define NREC 16      // uint32 slots per (t,g) record (64B)
#define TCH 16       // timesteps per routing thread

// ---- scratch (static __device__ globals) ----
__device__ float         g_pre [(size_t)TS * NG * NREC];   // ~187 MB
__device__ unsigned char g_gate[(size_t)TS * NG];
__device__ float         g_surf[(size_t)TS * NG];
__device__ float         g_base[(size_t)TS * NG];
__device__ float         g_uh  [2 * 15 * NG];

__constant__ float c_lo[32] = {0.f,0.5f,0.001f,0.3f,20.f,-8.f,1.f,0.1f,0.1f,1e-4f,1.f,1e-4f,0.1f,0.1f,50.f,-8.f,
                               1.f,-5.f,0.f,1.5f,0.f,0.01f,-1.f,0.f,0.f,0.f,50.f,50.f,0.3f,0.01f,0.5f,0.15f};
__constant__ float c_hi[32] = {1.f,3.f,3.f,1.f,300.f,-2.f,5.f,200.f,0.5f,0.9999f,50.f,0.9999f,50.f,100.f,500.f,-2.f,
                               5.f,2.f,5.f,3.f,5.f,0.2f,1.f,0.4f,1.f,1.f,500.f,500.f,20.f,5.f,13.f,1.5f};

__device__ __forceinline__ float sigm(float x) { return 1.f / (1.f + __expf(-x)); }
__device__ __forceinline__ float clip01(float x) { return fminf(fmaxf(x, 1e-6f), 1.f); }
__device__ __forceinline__ void prefetchL2(const void* p) {
    asm volatile("prefetch.global.L2 [%0];" :: "l"(p));
}
// expm1 for x in [0, 0.5]: Horner, rel err < 4e-6.
__device__ __forceinline__ float expm1_poly(float x) {
    float r = 1.f/720.f;
    r = fmaf(r, x, 1.f/120.f);
    r = fmaf(r, x, 1.f/24.f);
    r = fmaf(r, x, 1.f/6.f);
    r = fmaf(r, x, 0.5f);
    r = fmaf(r, x, 1.f);
    return r * x;
}
__device__ __forceinline__ float2 h2pair(float v) {
    unsigned u = __float_as_uint(v);
    __half2 h = *reinterpret_cast<__half2*>(&u);
    return __half22float2(h);
}
__device__ __forceinline__ unsigned packh2(float a, float b) {
    __half2 h = __floats2half2_rn(a, b);
    return *reinterpret_cast<unsigned*>(&h);
}

// ============================================================================
// Kernel 1: per-(t,g) preprocess — softmax -> fp16 pairs, gate bits, met.
// ============================================================================
__global__ void prep_kernel(const float* __restrict__ xphy, const float* __restrict__ wts) {
    size_t i = (size_t)blockIdx.x * blockDim.x + threadIdx.x;
    if (i >= (size_t)TS * NG) return;
    const float4* wsrc = (const float4*)(wts + i * 24);
    float v[24];
#pragma unroll
    for (int k = 0; k < 6; k++) {
        float4 q = wsrc[k];
        v[4*k] = q.x; v[4*k+1] = q.y; v[4*k+2] = q.z; v[4*k+3] = q.w;
    }
    float w[18];
#pragma unroll
    for (int grp = 0; grp < 3; grp++) {
        float m = v[grp*6];
#pragma unroll
        for (int k = 1; k < 6; k++) m = fmaxf(m, v[grp*6 + k]);
        float e[6], s = 0.f;
#pragma unroll
        for (int k = 0; k < 6; k++) { e[k] = __expf(v[grp*6 + k] - m); s += e[k]; }
        float inv = 1.f / s;
#pragma unroll
        for (int k = 0; k < 6; k++) w[grp*6 + k] = e[k] * inv;
    }
    unsigned bits = 0;
#pragma unroll
    for (int k = 0; k < 6; k++) bits |= (v[18 + k] > 0.f) ? (1u << k) : 0u;

    unsigned o[16];
#pragma unroll
    for (int k = 0; k < 9; k++) o[k] = packh2(w[2*k], w[2*k+1]);
    o[9]  = bits;
    o[10] = __float_as_uint(xphy[i*3 + 0]);   // prcp
    o[11] = __float_as_uint(xphy[i*3 + 1]);   // temp
    o[12] = __float_as_uint(xphy[i*3 + 2]);   // pet
    o[13] = 0u; o[14] = 0u; o[15] = 0u;

    float4* dst = (float4*)(g_pre + i * NREC);
#pragma unroll
    for (int k = 0; k < 4; k++)
        dst[k] = make_float4(__uint_as_float(o[4*k]), __uint_as_float(o[4*k+1]),
                             __uint_as_float(o[4*k+2]), __uint_as_float(o[4*k+3]));
    g_gate[i] = (unsigned char)bits;
}

// ============================================================================
// Kernel 2: per-cell unit-hydrograph weights
// ============================================================================
__global__ void uh_kernel(const float* __restrict__ hyb) {
    int g = blockIdx.x * blockDim.x + threadIdx.x;
    if (g >= NG) return;
    const float* h = hyb + (size_t)g * 32;
    float a1 = c_lo[28] + sigm(h[28]) * (c_hi[28] - c_lo[28]);
    float b1 = c_lo[29] + sigm(h[29]) * (c_hi[29] - c_lo[29]);
    float a2 = c_lo[30] + sigm(h[30]) * (c_hi[30] - c_lo[30]);
    float b2 = c_lo[31] + sigm(h[31]) * (c_hi[31] - c_lo[31]);
    float ib1 = 1.f / b1, ib2 = 1.f / b2;
    float lw1[15], lw2[15], m1 = -1e30f, m2 = -1e30f;
#pragma unroll
    for (int k = 0; k < 15; k++) {
        float kk = (float)(k + 1);
        float lk = __logf(kk);
        lw1[k] = (a1 - 1.f) * lk - kk * ib1;
        lw2[k] = (a2 - 1.f) * lk - kk * ib2;
        m1 = fmaxf(m1, lw1[k]); m2 = fmaxf(m2, lw2[k]);
    }
    float e1[15], e2[15], s1 = 0.f, s2 = 0.f;
#pragma unroll
    for (int k = 0; k < 15; k++) {
        e1[k] = __expf(lw1[k] - m1); s1 += e1[k];
        e2[k] = __expf(lw2[k] - m2); s2 += e2[k];
    }
    float i1 = 1.f / s1, i2 = 1.f / s2;
#pragma unroll
    for (int k = 0; k < 15; k++) {
        g_uh[k * NG + g]        = e1[k] * i1;
        g_uh[(15 + k) * NG + g] = e2[k] * i2;
    }
}

// ============================================================================
// One scan step (exact R15 math).
// ============================================================================
struct SP {
    float ddfmin, ddfplus, Kcum, swi, msw1, inv_m1, inv_m2;
    float inf_pc, hbv_beta, vic_b, hm_a, cc;
    float perc_coef, perc_sfc, crise;
    float inv_x3a, p10a, bfn1, bfmax1, lam, c_lam, thresh, c_th;
    float inv_x3b, p10b, bfn2, bfmax2;
    float Tbf, Kf, Tbm;
};

__device__ __forceinline__ void scan_step(
    const SP& sp, int t, int g,
    float& snow, float& liq, float& cum, float& sw1, float& sw2,
    const float4& c0, const float4& c1, const float4& c2, const float4& c3)
{
    float2 pw0 = h2pair(c0.x), pw1 = h2pair(c0.y), pw2 = h2pair(c0.z);
    float2 pa0 = h2pair(c0.w), pa1 = h2pair(c1.x), pa2 = h2pair(c1.y);
    float2 pb0 = h2pair(c1.z), pb1 = h2pair(c1.w), pb2 = h2pair(c2.x);
    const float wi0 = pw0.x, wi1 = pw0.y, wi2 = pw1.x, wi3 = pw1.y, wi4 = pw2.x, wi5 = pw2.y;
    const float wa0 = pa0.x, wa1 = pa0.y, wa2 = pa1.x, wa3 = pa1.y, wa4 = pa2.x, wa5 = pa2.y;
    const float wb0 = pb0.x, wb1 = pb0.y, wb2 = pb1.x, wb3 = pb1.y, wb4 = pb2.x, wb5 = pb2.y;
    const unsigned bits = __float_as_uint(c2.y);
    const float prcp = c2.z, temp = c2.w, pet = c3.x;
    const float gb0 = (bits & 1u)        ? 1.f : 0.f;
    const float gb1 = ((bits >> 1) & 1u) ? 1.f : 0.f;
    const float gb2 = ((bits >> 2) & 1u) ? 1.f : 0.f;
    const float gb3 = ((bits >> 3) & 1u) ? 1.f : 0.f;

    // --- snow module ---
    float rain  = (temp >= 0.f) ? prcp : 0.f;
    float snowf = (temp <  0.f) ? prcp : 0.f;
    float canopy = pet * sp.cc;
    rain  = fmaxf(rain  - canopy * gb2, 0.f);
    snowf = fmaxf(snowf - canopy * gb3, 0.f);
    float refreeze = fminf(liq, sp.Kf * fmaxf(sp.Tbf - temp, 0.f));
    snow = snow + snowf + refreeze;
    liq  = liq - refreeze;
    float ddf  = sp.ddfmin + sp.ddfplus * (1.f - __expf(-sp.Kcum * cum));
    float melt = fminf(snow, ddf * fmaxf(temp - sp.Tbm, 0.f));
    snow -= melt;
    cum = (snow < 1e-6f) ? 1e-6f : (cum + melt);
    liq += melt;
    float overflow = fmaxf(liq - sp.swi * snow, 0.f);
    liq -= overflow;
    float wavail = rain + overflow;

    // --- infiltration blend ---
    float sat1 = clip01(sw1 * sp.inv_m1);
    float dry1 = clip01(1.f - sat1);
    float o1 = 1.f - __powf(sat1, sp.hbv_beta);
    float o2 = __powf(dry1, sp.vic_b);
    float fsum = wi0 * sp.inf_pc + wi1 * o1 + wi2 * o2 + wi3 * (sp.hm_a * dry1)
               + wi4 * (1.f - sat1 * sat1) + wi5;
    float infil = wavail * fsum;
    sw1 += infil;
    float excess = fmaxf(sw1 - sp.msw1, 0.f);
    sw1 -= excess;
    float surf = wavail - infil + excess;

    // --- percolation / capillary rise / ET ---
    sat1 = clip01(sw1 * sp.inv_m1);
    float perc = gb0 * sp.perc_coef * fmaxf(sat1 - sp.perc_sfc, 0.f);
    perc = fminf(perc, sw1);
    sw1 -= perc; sw2 += perc;
    float sat2 = clip01(sw2 * sp.inv_m2);
    sat1 = clip01(sw1 * sp.inv_m1);
    float capi = fminf(gb1 * sp.crise * (1.f - sat1) * sat2, sw2);
    sw2 -= capi; sw1 += capi;
    sat1 = clip01(sw1 * sp.inv_m1);
    float et = fminf(pet * sat1, sw1);
    sw1 -= et;
    sat1 = clip01(sw1 * sp.inv_m1);

    // --- baseflow 1 blend ---   (1+r^4)^(-1/4) == sqrtf(rsqrtf(q))
    float ra = sw1 * sp.inv_x3a; float ra2 = ra * ra; float qa = 1.f + ra2 * ra2;
    float b0v = sw1 * (1.f - sqrtf(rsqrtf(qa)));
    float b1v = sp.p10a * sw1;
    float b2v = sp.bfmax1 * __powf(sat1, sp.bfn1);
    float b3v = sp.bfmax1 * sat1;
    float b4v = sp.c_lam * expm1_poly(sp.lam * sat1);
    float b5v = sp.c_th * fmaxf(sat1 - sp.thresh, 0.f);
    float bf1 = fminf(wa0*b0v + wa1*b1v + wa2*b2v + wa3*b3v + wa4*b4v + wa5*b5v, sw1);
    sw1 -= bf1;

    // --- baseflow 2 blend ---
    float s2c = clip01(sw2 * sp.inv_m2);
    float rb = sw2 * sp.inv_x3b; float rb2 = rb * rb; float qb = 1.f + rb2 * rb2;
    float d0 = sw2 * (1.f - sqrtf(rsqrtf(qb)));
    float d1 = sp.p10b * sw2;
    float d2 = sp.bfmax2 * __powf(s2c, sp.bfn2);
    float d3 = sp.bfmax2 * s2c;
    float d4 = sp.bfmax2 * s2c * s2c;
    float d5 = d1 * s2c;
    float bf2 = fminf(wb0*d0 + wb1*d1 + wb2*d2 + wb3*d3 + wb4*d4 + wb5*d5, sw2);
    sw2 -= bf2;

    g_surf[(size_t)t * NG + g] = surf;
    g_base[(size_t)t * NG + g] = bf1 + bf2;
}

// ============================================================================
// Kernel 3: sequential scan — unroll x2, DEPTH-3.5 register pipeline.
// Ring of 5 record buffers; loads issue ~3.5 bodies before consumption,
// covering worst-case DRAM latency instead of relying on L2 prefetch alone.
// ============================================================================
__global__ void __launch_bounds__(32, 1) scan_kernel(const float* __restrict__ hyb) {
    int g = blockIdx.x * 32 + threadIdx.x;
    if (g >= NG) return;
    const float* h = hyb + (size_t)g * 32;
    float P[32];
#pragma unroll
    for (int i = 0; i < 32; i++) P[i] = c_lo[i] + sigm(h[i]) * (c_hi[i] - c_lo[i]);

    SP sp;
    sp.cc = P[24] * (1.f - P[25]);
    sp.Tbf = P[17]; sp.Kf = P[18]; sp.ddfmin = P[19]; sp.ddfplus = P[20];
    sp.Kcum = P[21]; sp.Tbm = P[22]; sp.swi = P[23];
    sp.msw1 = P[26]; sp.inv_m1 = 1.f / P[26]; sp.inv_m2 = 1.f / P[27];
    sp.inf_pc = P[0]; sp.hbv_beta = P[1]; sp.vic_b = P[2]; sp.hm_a = P[3];
    sp.perc_coef = P[10] / (1.f - P[11]); sp.perc_sfc = P[11]; sp.crise = P[12];
    sp.inv_x3a = 1.f / P[4];
    sp.p10a = exp2f(P[5] * 3.3219280948873623f);
    sp.bfn1 = P[6]; sp.bfmax1 = P[7]; sp.lam = P[8];
    sp.c_lam = P[7] / expm1f(P[8]);
    sp.thresh = P[9]; sp.c_th = P[7] / (1.f - P[9]);
    sp.inv_x3b = 1.f / P[14];
    sp.p10b = exp2f(P[15] * 3.3219280948873623f);
    sp.bfn2 = P[16]; sp.bfmax2 = P[13];

    float snow = 1e-6f, liq = 1e-6f, cum = 1e-6f, sw1 = 1e-6f, sw2 = 1e-6f;

    const float4* rec = (const float4*)g_pre;
    // prologue: load t = 0,1,2 into c, n, m
    size_t r0 = ((size_t)0 * NG + g) * 4;
    size_t r1 = ((size_t)1 * NG + g) * 4;
    size_t rm = ((size_t)2 * NG + g) * 4;
    float4 c0 = __ldcs(rec+r0), c1 = __ldcs(rec+r0+1), c2 = __ldcs(rec+r0+2), c3 = __ldcs(rec+r0+3);
    float4 n0 = __ldcs(rec+r1), n1 = __ldcs(rec+r1+1), n2 = __ldcs(rec+r1+2), n3 = __ldcs(rec+r1+3);
    float4 m0 = __ldcs(rec+rm), m1 = __ldcs(rec+rm+1), m2 = __ldcs(rec+rm+2), m3 = __ldcs(rec+rm+3);
#pragma unroll
    for (int tp = 3; tp < 10; tp++)
        prefetchL2((const char*)(rec + ((size_t)tp * NG + g) * 4));

#pragma unroll 1
    for (int t = 0; t < TS; t += 2) {
        // L2 prefetch two lines ~10 steps ahead
        int tp0 = t + 10; if (tp0 >= TS) tp0 = TS - 1;
        int tp1 = t + 11; if (tp1 >= TS) tp1 = TS - 1;
        prefetchL2((const char*)(rec + ((size_t)tp0 * NG + g) * 4));
        prefetchL2((const char*)(rec + ((size_t)tp1 * NG + g) * 4));

        // issue loads for t+3 (consumed as body B of iteration t+2)
        int t3 = t + 3; if (t3 >= TS) t3 = TS - 1;
        size_t r3 = ((size_t)t3 * NG + g) * 4;
        float4 q0 = __ldcs(rec+r3),  q1 = __ldcs(rec+r3+1),
               q2 = __ldcs(rec+r3+2), q3 = __ldcs(rec+r3+3);

        // body A: step t
        scan_step(sp, t, g, snow, liq, cum, sw1, sw2, c0, c1, c2, c3);

        // issue loads for t+4 (consumed as body A of iteration t+4)
        int t4 = t + 4; if (t4 >= TS) t4 = TS - 1;
        size_t r4 = ((size_t)t4 * NG + g) * 4;
        float4 e0 = __ldcs(rec+r4),  e1 = __ldcs(rec+r4+1),
               e2 = __ldcs(rec+r4+2), e3 = __ldcs(rec+r4+3);

        // body B: step t+1
        scan_step(sp, t + 1, g, snow, liq, cum, sw1, sw2, n0, n1, n2, n3);

        // rotate ring: c <- m(t+2), n <- q(t+3), m <- e(t+4)
        c0 = m0; c1 = m1; c2 = m2; c3 = m3;
        n0 = q0; n1 = q1; n2 = q2; n3 = q3;
        m0 = e0; m1 = e1; m2 = e2; m3 = e3;
    }
}

// ============================================================================
// Kernel 4: 15-tap UH routing + gating + final sum.
// ============================================================================
__global__ void __launch_bounds__(128) route_kernel(float* __restrict__ out) {
    int g  = blockIdx.x * 128 + threadIdx.x;
    int t0 = blockIdx.y * TCH;
    if (g >= NG) return;
    float u1[15], u2[15];
#pragma unroll
    for (int k = 0; k < 15; k++) {
        u1[k] = g_uh[k * NG + g];
        u2[k] = g_uh[(15 + k) * NG + g];
    }
    float s[TCH + 14], b[TCH + 14];
#pragma unroll
    for (int i = 0; i < TCH + 14; i++) {
        int tt = t0 - 14 + i;
        bool ok = (tt >= 0) && (tt < TS);
        s[i] = ok ? g_surf[(size_t)tt * NG + g] : 0.f;
        b[i] = ok ? g_base[(size_t)tt * NG + g] : 0.f;
    }
#pragma unroll
    for (int j = 0; j < TCH; j++) {
        int t = t0 + j;
        if (t < TS) {
            float cs = 0.f, cb = 0.f;
#pragma unroll
            for (int l = 0; l < 15; l++) {
                cs += u1[l] * s[14 + j - l];
                cb += u2[l] * b[14 + j - l];
            }
            unsigned bits = g_gate[(size_t)t * NG + g];
            float g4 = (float)((bits >> 4) & 1);
            float g5 = (float)((bits >> 5) & 1);
            out[(size_t)t * NG + g] = g4 * cs + (1.f - g4) * s[14 + j]
                                    + g5 * cb + (1.f - g5) * b[14 + j];
        }
    }
}

// ============================================================================
extern "C" void kernel_launch(void* const* d_in, const int* in_sizes, int n_in,
                              void* d_out, int out_size) {
    const float* xphy = nullptr; const float* wts = nullptr; const float* hyb = nullptr;
    for (int i = 0; i < n_in; i++) {
        if (in_sizes[i] == TS * NG * 3)       xphy = (const float*)d_in[i];
        else if (in_sizes[i] == TS * NG * 24) wts  = (const float*)d_in[i];
        else if (in_sizes[i] == NG * 32)      hyb  = (const float*)d_in[i];
    }
    float* out = (float*)d_out;                  // (1460, 2000)

    size_t total = (size_t)TS * NG;
    prep_kernel<<<(unsigned)((total + 255) / 256), 256>>>(xphy, wts);
    uh_kernel<<<(NG + 127) / 128, 128>>>(hyb);
    scan_kernel<<<(NG + 31) / 32, 32>>>(hyb);
    dim3 rg((NG + 127) / 128, (TS + TCH - 1) / TCH);
    route_kernel<<<rg, 128>>>(out);
}